// round 14
// baseline (speedup 1.0000x reference)
#include <cuda_runtime.h>
#include <cuda_fp16.h>
#include <math.h>
#include <stdint.h>

// Problem constants
#define BB   4
#define SS   2048
#define DD   1024
#define HH   16
#define DK   64
#define MROWS (BB * SS)   // 8192

// 0.125 * log2(e): folds softmax scale + base-2 exp into Q projection
#define QSCALE 0.18033688011112042f

// ---------------------------------------------------------------------------
// Device scratch (allocations forbidden -> __device__ globals)
// ---------------------------------------------------------------------------
__device__ __half g_A[3 * MROWS * DD];          // q,k,v activations fp16
__device__ __half g_Wt[4 * DD * DD];            // weights transposed [N][K] fp16
__device__ __half g_Ph[3 * BB * HH * SS * DK];  // head-split Q,K,V fp16
__device__ __half g_Oh[MROWS * DD];             // attn output fp16 (O-proj input)

// ---------------------------------------------------------------------------
// PTX helpers (base-target sm_80+; nothing 'a'-gated)
// ---------------------------------------------------------------------------
__device__ __forceinline__ uint32_t smem_u32(const void* p) {
    uint32_t a;
    asm("{ .reg .u64 t; cvta.to.shared.u64 t, %1; cvt.u32.u64 %0, t; }" : "=r"(a) : "l"(p));
    return a;
}
__device__ __forceinline__ void cp_async16(uint32_t s, const void* g) {
    asm volatile("cp.async.cg.shared.global [%0], [%1], 16;" :: "r"(s), "l"(g));
}
__device__ __forceinline__ void cp_commit() {
    asm volatile("cp.async.commit_group;" ::: "memory");
}
template <int N>
__device__ __forceinline__ void cp_wait() {
    asm volatile("cp.async.wait_group %0;" :: "n"(N) : "memory");
}
__device__ __forceinline__ void ldsm4(uint32_t* r, uint32_t a) {
    asm volatile("ldmatrix.sync.aligned.m8n8.x4.shared.b16 {%0,%1,%2,%3}, [%4];"
                 : "=r"(r[0]), "=r"(r[1]), "=r"(r[2]), "=r"(r[3]) : "r"(a));
}
__device__ __forceinline__ void ldsm4t(uint32_t* r, uint32_t a) {
    asm volatile("ldmatrix.sync.aligned.m8n8.x4.trans.shared.b16 {%0,%1,%2,%3}, [%4];"
                 : "=r"(r[0]), "=r"(r[1]), "=r"(r[2]), "=r"(r[3]) : "r"(a));
}
// x2 variant: only lanes 0-15 supply addresses
__device__ __forceinline__ void ldsm2t(uint32_t* r, uint32_t a) {
    asm volatile("ldmatrix.sync.aligned.m8n8.x2.trans.shared.b16 {%0,%1}, [%2];"
                 : "=r"(r[0]), "=r"(r[1]) : "r"(a));
}
__device__ __forceinline__ void mma16816(float* d, const uint32_t* a, const uint32_t* b) {
    asm volatile(
        "mma.sync.aligned.m16n8k16.row.col.f32.f16.f16.f32 "
        "{%0,%1,%2,%3}, {%4,%5,%6,%7}, {%8,%9}, {%0,%1,%2,%3};"
        : "+f"(d[0]), "+f"(d[1]), "+f"(d[2]), "+f"(d[3])
        : "r"(a[0]), "r"(a[1]), "r"(a[2]), "r"(a[3]), "r"(b[0]), "r"(b[1]));
}
__device__ __forceinline__ uint32_t packh(float x, float y) {
    __half2 t = __floats2half2_rn(x, y);
    return *(uint32_t*)&t;
}
// packed 2^x on two fp16 lanes (single MUFU op)
__device__ __forceinline__ uint32_t ex2h2(uint32_t x) {
    uint32_t y;
    asm("ex2.approx.f16x2 %0, %1;" : "=r"(y) : "r"(x));
    return y;
}

// ---------------------------------------------------------------------------
// Conversions
// ---------------------------------------------------------------------------
__global__ void convert_act(const float* __restrict__ x0, const float* __restrict__ x1,
                            const float* __restrict__ x2)
{
    const int z = blockIdx.y;
    const float* x = (z == 0) ? x0 : (z == 1) ? x1 : x2;
    __half* dst = g_A + (size_t)z * MROWS * DD;

    const size_t i = (size_t)blockIdx.x * blockDim.x + threadIdx.x;
    float4 v = ((const float4*)x)[i];
    ((__half2*)dst)[2 * i + 0] = __floats2half2_rn(v.x, v.y);
    ((__half2*)dst)[2 * i + 1] = __floats2half2_rn(v.z, v.w);
}

// Weight transpose + round: Wt[n][k] = fp16(w[k][n])
__global__ void convert_wt(const float* __restrict__ w0, const float* __restrict__ w1,
                           const float* __restrict__ w2, const float* __restrict__ w3)
{
    __shared__ float t[32][33];
    const int z = blockIdx.z;
    const float* w = (z == 0) ? w0 : (z == 1) ? w1 : (z == 2) ? w2 : w3;
    const int nb = blockIdx.x * 32;
    const int kb = blockIdx.y * 32;

    for (int i = threadIdx.y; i < 32; i += 8)
        t[i][threadIdx.x] = w[(size_t)(kb + i) * DD + nb + threadIdx.x];
    __syncthreads();

    __half* wt = g_Wt + (size_t)z * DD * DD;
    for (int i = threadIdx.y; i < 32; i += 8)
        wt[(size_t)(nb + i) * DD + kb + threadIdx.x] = __float2half_rn(t[threadIdx.x][i]);
}

// ---------------------------------------------------------------------------
// HMMA single-fp16 GEMM: C = A @ W^T + bias   (R11/R12 tiling; single-sync
// pipeline: wait -> sync -> issue-next -> compute. One barrier per chunk.)
// CTA 128x128, K-chunk 32, 4 warps, warp-tile 64x64, 2-stage, 2 CTAs/SM.
// ---------------------------------------------------------------------------
#define PLANE_BYTES 10240           // 128 * 80
#define BUF_BYTES   (2 * PLANE_BYTES)
#define GEMM_SMEM   (2 * BUF_BYTES) // 40960

__global__ __launch_bounds__(128, 2)
void gemm_tc(const float* __restrict__ bias0, const float* __restrict__ bias1,
             const float* __restrict__ bias2, float* __restrict__ outExt, int mode)
{
    extern __shared__ __align__(128) char smem[];
    const uint32_t smemA = smem_u32(smem);

    const int tid  = threadIdx.x;
    const int wid  = tid >> 5;
    const int lane = tid & 31;
    const int wm   = wid >> 1;
    const int wn   = wid & 1;
    const int z    = blockIdx.z;
    const int mBase = blockIdx.x * 128;
    const int nBase = blockIdx.y * 128;

    const __half* A = (mode == 0) ? (g_A + (size_t)z * MROWS * DD) : g_Oh;
    const int widx = (mode == 0) ? z : 3;
    const __half* W = g_Wt + (size_t)widx * DD * DD;
    const float* bias = (z == 0) ? bias0 : (z == 1) ? bias1 : bias2;

    const __half* srcs[2] = {A, W};

    auto load_chunk = [&](int buf, int k0) {
        char* bb = smem + buf * BUF_BYTES;
        #pragma unroll
        for (int it = 0; it < 8; it++) {
            const int idx = it * 128 + tid;      // 0..1023
            const int p   = idx >> 9;            // 0 = A; 1 = W
            const int r   = idx & 511;
            const int row = r >> 2;
            const int seg = r & 3;
            const int rowBase = (p == 0) ? mBase : nBase;
            const __half* g = srcs[p] + (size_t)(rowBase + row) * DD + k0 + seg * 8;
            cp_async16(smem_u32(bb + p * PLANE_BYTES + row * 80 + seg * 16), g);
        }
    };

    float acc[4][8][4];
    #pragma unroll
    for (int t = 0; t < 4; t++)
        #pragma unroll
        for (int n = 0; n < 8; n++)
            #pragma unroll
            for (int j = 0; j < 4; j++) acc[t][n][j] = 0.f;

    const int aRow = lane & 15;
    const int aCol = (lane >> 4) * 16;
    const int bRow = (lane & 7) + ((lane >> 4) << 3);
    const int bCol = ((lane >> 3) & 1) * 16;

    const int NC = DD / 32;   // 32 chunks

    load_chunk(0, 0);
    cp_commit();

    for (int c = 0; c < NC; c++) {
        const int buf = c & 1;
        // Tile c's group is the only one outstanding (issued last iter or
        // prologue, one full compute phase ago).
        cp_wait<0>();
        __syncthreads();   // visibility of tile c + all readers of buf^1 done
        if (c + 1 < NC) {
            load_chunk(buf ^ 1, (c + 1) * 32);
            cp_commit();
        }

        const uint32_t base = smemA + buf * BUF_BYTES;
        #pragma unroll
        for (int s = 0; s < 2; s++) {
            uint32_t ah[4][4], bh[8][2];
            #pragma unroll
            for (int t = 0; t < 4; t++)
                ldsm4(ah[t], base + (wm * 64 + t * 16 + aRow) * 80 + s * 32 + aCol);
            #pragma unroll
            for (int bt = 0; bt < 4; bt++) {
                const uint32_t addr = base + PLANE_BYTES
                                    + (wn * 64 + bt * 16 + bRow) * 80 + s * 32 + bCol;
                uint32_t r4[4];
                ldsm4(r4, addr);
                bh[bt * 2][0] = r4[0]; bh[bt * 2][1] = r4[1];
                bh[bt * 2 + 1][0] = r4[2]; bh[bt * 2 + 1][1] = r4[3];
            }
            #pragma unroll
            for (int t = 0; t < 4; t++)
                #pragma unroll
                for (int n = 0; n < 8; n++)
                    mma16816(acc[t][n], ah[t], bh[n]);
        }
    }

    // ---- epilogue ----
    const int rBase = mBase + wm * 64 + (lane >> 2);
    const int cBase = nBase + wn * 64 + (lane & 3) * 2;
    const float csc = (mode == 0 && z == 0) ? QSCALE : 1.0f;
    __half* ph = g_Ph + (size_t)z * BB * HH * SS * DK;

    #pragma unroll
    for (int t = 0; t < 4; t++) {
        #pragma unroll
        for (int n = 0; n < 8; n++) {
            const int col = cBase + n * 8;
            const float b0v = bias[col];
            const float b1v = bias[col + 1];
            #pragma unroll
            for (int half = 0; half < 2; half++) {
                const int row = rBase + t * 16 + half * 8;
                float v0 = (acc[t][n][half * 2 + 0] + b0v) * csc;
                float v1 = (acc[t][n][half * 2 + 1] + b1v) * csc;
                if (mode == 0) {
                    const int b = row >> 11;
                    const int s = row & 2047;
                    const int h = col >> 6;
                    const int dk = col & 63;
                    const size_t o = (((size_t)(b * HH + h)) * SS + s) * DK + dk;
                    *(__half2*)&ph[o] = __floats2half2_rn(v0, v1);
                } else {
                    float2 v; v.x = v0; v.y = v1;
                    *(float2*)&outExt[(size_t)row * DD + col] = v;
                }
            }
        }
    }
}

// ---------------------------------------------------------------------------
// Tensor-core flash attention. R13 config (4 warps x 32 q-rows, f16x2 exp,
// ones-column row-sum) with the single-sync pipeline: one barrier per tile.
// Smem: K,V planes 64 rows x 144B, double buffered = 36864 B. 2 CTAs/SM.
// ---------------------------------------------------------------------------
#define ARS    144                  // attn smem row stride (bytes)
#define APLANE (64 * ARS)           // 9216
#define ABUF   (2 * APLANE)         // 18432
#define ATTN_SMEM (2 * ABUF)        // 36864

__global__ __launch_bounds__(128, 2)
void attn_tc()
{
    extern __shared__ __align__(128) char smem[];
    const uint32_t smemA = smem_u32(smem);

    const int tid  = threadIdx.x;
    const int wid  = tid >> 5;       // 0..3, owns q-rows wid*32 .. wid*32+31
    const int lane = tid & 31;
    const int b = blockIdx.z;
    const int h = blockIdx.y;
    const int qBase = blockIdx.x * 128;

    const size_t hb = ((size_t)(b * HH + h)) * SS * DK;
    const size_t PS = (size_t)BB * HH * SS * DK;
    const __half* Qh = g_Ph + hb;
    const __half* Kh = g_Ph + PS + hb;
    const __half* Vh = g_Ph + 2 * PS + hb;

    // ---- stage Q (128 rows x 64 dk) through smem, load to regs ----
    {
        #pragma unroll
        for (int it = 0; it < 8; it++) {
            const int idx = it * 128 + tid;        // 0..1023
            const int row = idx >> 3;
            const int seg = idx & 7;
            cp_async16(smemA + row * ARS + seg * 16,
                       Qh + (size_t)(qBase + row) * DK + seg * 8);
        }
        cp_commit();
        cp_wait<0>();
        __syncthreads();
    }

    uint32_t qh[2][4][4];    // [q-subtile][dk-slice][frag]
    {
        const int aRow = lane & 15;
        const int aCol = (lane >> 4) * 16;
        #pragma unroll
        for (int u = 0; u < 2; u++)
            #pragma unroll
            for (int s = 0; s < 4; s++)
                ldsm4(qh[u][s],
                      smemA + (wid * 32 + u * 16 + aRow) * ARS + s * 32 + aCol);
    }
    __syncthreads();   // Q regs extracted; smem reusable

    // ---- ones column: V-plane padding bytes [128..144) of every row gets
    // {1.0h, 0,...}. cp.async only writes bytes [0..128) per row, so these
    // persist once set.
    {
        const int st  = tid >> 6;                 // 0..1 (stage)
        const int row = tid & 63;
        int4 ones = make_int4(0x00003C00, 0, 0, 0);
        *(int4*)(smem + st * ABUF + APLANE + row * ARS + 128) = ones;
    }

    // ---- K/V tile loader ----
    auto load_kv = [&](int buf, int t0) {
        char* bb = smem + buf * ABUF;
        #pragma unroll
        for (int it = 0; it < 8; it++) {
            const int idx = it * 128 + tid;        // 0..1023
            const int p   = idx >> 9;              // 0=K 1=V
            const int r   = idx & 511;
            const int row = r >> 3;
            const int seg = r & 7;
            const __half* g = (p ? Vh : Kh) + (size_t)(t0 + row) * DK + seg * 8;
            cp_async16(smem_u32(bb + p * APLANE + row * ARS + seg * 16), g);
        }
    };

    float oacc[2][8][4];
    #pragma unroll
    for (int u = 0; u < 2; u++)
        #pragma unroll
        for (int n = 0; n < 8; n++)
            #pragma unroll
            for (int j = 0; j < 4; j++) oacc[u][n][j] = 0.f;
    float oext[2][4];
    #pragma unroll
    for (int u = 0; u < 2; u++)
        #pragma unroll
        for (int j = 0; j < 4; j++) oext[u][j] = 0.f;

    const int bRow = (lane & 7) + ((lane >> 4) << 3);
    const int bCol = ((lane >> 3) & 1) * 16;
    const int vRow = lane & 15;
    const int vCol = (lane >> 4) * 16;

    load_kv(0, 0);
    cp_commit();

    const int NT = SS / 64;   // 32 key tiles

    for (int t = 0; t < NT; t++) {
        const int buf = t & 1;
        // Tile t's group is the only one outstanding.
        cp_wait<0>();
        __syncthreads();   // visibility of tile t + all readers of buf^1 done
        if (t + 1 < NT) {
            load_kv(buf ^ 1, (t + 1) * 64);
            cp_commit();
        }

        const uint32_t kbase = smemA + buf * ABUF;
        const uint32_t vbase = kbase + APLANE;

        // ---- S = Q K^T (K fragments shared across both q-subtiles) ----
        float sc[2][8][4];
        #pragma unroll
        for (int u = 0; u < 2; u++)
            #pragma unroll
            for (int n = 0; n < 8; n++)
                #pragma unroll
                for (int j = 0; j < 4; j++) sc[u][n][j] = 0.f;

        #pragma unroll
        for (int s = 0; s < 4; s++) {
            uint32_t bh[8][2];
            #pragma unroll
            for (int bt = 0; bt < 4; bt++) {
                const uint32_t addr = kbase + (bt * 16 + bRow) * ARS + s * 32 + bCol;
                uint32_t r4[4];
                ldsm4(r4, addr);
                bh[bt * 2][0] = r4[0]; bh[bt * 2][1] = r4[1];
                bh[bt * 2 + 1][0] = r4[2]; bh[bt * 2 + 1][1] = r4[3];
            }
            #pragma unroll
            for (int u = 0; u < 2; u++)
                #pragma unroll
                for (int n = 0; n < 8; n++)
                    mma16816(sc[u][n], qh[u][s], bh[n]);
        }

        // ---- O += P V with P = 2^S in packed fp16; l via ones column ----
        #pragma unroll
        for (int j = 0; j < 4; j++) {
            uint32_t vb[8][2];
            #pragma unroll
            for (int d = 0; d < 4; d++) {
                const uint32_t addr = vbase + (j * 16 + vRow) * ARS + d * 32 + vCol;
                uint32_t r4[4];
                ldsm4t(r4, addr);
                vb[d * 2][0] = r4[0]; vb[d * 2][1] = r4[1];
                vb[d * 2 + 1][0] = r4[2]; vb[d * 2 + 1][1] = r4[3];
            }
            uint32_t ob[2];
            ldsm2t(ob, vbase + (j * 16 + vRow) * ARS + 128);

            #pragma unroll
            for (int u = 0; u < 2; u++) {
                uint32_t aph[4];
                aph[0] = ex2h2(packh(sc[u][2*j][0],   sc[u][2*j][1]));
                aph[1] = ex2h2(packh(sc[u][2*j][2],   sc[u][2*j][3]));
                aph[2] = ex2h2(packh(sc[u][2*j+1][0], sc[u][2*j+1][1]));
                aph[3] = ex2h2(packh(sc[u][2*j+1][2], sc[u][2*j+1][3]));
                #pragma unroll
                for (int n = 0; n < 8; n++)
                    mma16816(oacc[u][n], aph, vb[n]);
                mma16816(oext[u], aph, ob);
            }
        }
    }

    // ---- l in quad-leader's oext[u][0]/oext[u][2]; normalize, write ----
    #pragma unroll
    for (int u = 0; u < 2; u++) {
        const float l0v = __shfl_sync(0xffffffffu, oext[u][0], lane & 28);
        const float l1v = __shfl_sync(0xffffffffu, oext[u][2], lane & 28);
        const float inv0 = 1.f / l0v;
        const float inv1 = 1.f / l1v;
        const int s0 = qBase + wid * 32 + u * 16 + (lane >> 2);
        const int s1 = s0 + 8;
        #pragma unroll
        for (int n = 0; n < 8; n++) {
            const int col = h * 64 + n * 8 + (lane & 3) * 2;
            *(__half2*)&g_Oh[((size_t)(b * SS + s0)) * DD + col] =
                __floats2half2_rn(oacc[u][n][0] * inv0, oacc[u][n][1] * inv0);
            *(__half2*)&g_Oh[((size_t)(b * SS + s1)) * DD + col] =
                __floats2half2_rn(oacc[u][n][2] * inv1, oacc[u][n][3] * inv1);
        }
    }
}

// ---------------------------------------------------------------------------
extern "C" void kernel_launch(void* const* d_in, const int* in_sizes, int n_in,
                              void* d_out, int out_size)
{
    const float* q  = (const float*)d_in[0];
    const float* k  = (const float*)d_in[1];
    const float* v  = (const float*)d_in[2];
    const float* wq = (const float*)d_in[3];
    const float* bq = (const float*)d_in[4];
    const float* wk = (const float*)d_in[5];
    const float* bk = (const float*)d_in[6];
    const float* wv = (const float*)d_in[7];
    const float* bv = (const float*)d_in[8];
    const float* wo = (const float*)d_in[9];
    const float* bo = (const float*)d_in[10];
    float* out = (float*)d_out;

    cudaFuncSetAttribute(gemm_tc, cudaFuncAttributeMaxDynamicSharedMemorySize, GEMM_SMEM);
    cudaFuncSetAttribute(attn_tc, cudaFuncAttributeMaxDynamicSharedMemorySize, ATTN_SMEM);

    // 1) Round activations to fp16; transpose+round weights to fp16
    convert_act<<<dim3(MROWS * DD / 4 / 256, 3), 256>>>(q, k, v);
    convert_wt<<<dim3(32, 32, 4), dim3(32, 8)>>>(wq, wk, wv, wo);

    // 2) QKV projections -> fp16 head-split (Q pre-scaled by 0.125*log2e)
    gemm_tc<<<dim3(MROWS / 128, DD / 128, 3), 128, GEMM_SMEM>>>(bq, bk, bv, nullptr, 0);

    // 3) Tensor-core flash attention -> g_Oh
    attn_tc<<<dim3(SS / 128, HH, BB), 128, ATTN_SMEM>>>();

    // 4) O projection
    gemm_tc<<<dim3(MROWS / 128, DD / 128, 1), 128, GEMM_SMEM>>>(bo, bo, bo, out, 1);
}

// round 15
// speedup vs baseline: 1.0149x; 1.0149x over previous
#include <cuda_runtime.h>
#include <cuda_fp16.h>
#include <math.h>
#include <stdint.h>

// Problem constants
#define BB   4
#define SS   2048
#define DD   1024
#define HH   16
#define DK   64
#define MROWS (BB * SS)   // 8192

// 0.125 * log2(e): folds softmax scale + base-2 exp into Q projection
#define QSCALE 0.18033688011112042f

// ---------------------------------------------------------------------------
// Device scratch (allocations forbidden -> __device__ globals)
// ---------------------------------------------------------------------------
__device__ __half g_A[3 * MROWS * DD];          // q,k,v activations fp16
__device__ __half g_Wt[4 * DD * DD];            // weights transposed [N][K] fp16
__device__ __half g_Ph[3 * BB * HH * SS * DK];  // head-split Q,K,V fp16
__device__ __half g_Oh[MROWS * DD];             // attn output fp16 (O-proj input)

// ---------------------------------------------------------------------------
// PTX helpers (base-target sm_80+; nothing 'a'-gated)
// ---------------------------------------------------------------------------
__device__ __forceinline__ uint32_t smem_u32(const void* p) {
    uint32_t a;
    asm("{ .reg .u64 t; cvta.to.shared.u64 t, %1; cvt.u32.u64 %0, t; }" : "=r"(a) : "l"(p));
    return a;
}
__device__ __forceinline__ void cp_async16(uint32_t s, const void* g) {
    asm volatile("cp.async.cg.shared.global [%0], [%1], 16;" :: "r"(s), "l"(g));
}
__device__ __forceinline__ void cp_commit() {
    asm volatile("cp.async.commit_group;" ::: "memory");
}
template <int N>
__device__ __forceinline__ void cp_wait() {
    asm volatile("cp.async.wait_group %0;" :: "n"(N) : "memory");
}
__device__ __forceinline__ void ldsm4(uint32_t* r, uint32_t a) {
    asm volatile("ldmatrix.sync.aligned.m8n8.x4.shared.b16 {%0,%1,%2,%3}, [%4];"
                 : "=r"(r[0]), "=r"(r[1]), "=r"(r[2]), "=r"(r[3]) : "r"(a));
}
__device__ __forceinline__ void ldsm4t(uint32_t* r, uint32_t a) {
    asm volatile("ldmatrix.sync.aligned.m8n8.x4.trans.shared.b16 {%0,%1,%2,%3}, [%4];"
                 : "=r"(r[0]), "=r"(r[1]), "=r"(r[2]), "=r"(r[3]) : "r"(a));
}
// x2 variant: only lanes 0-15 supply addresses
__device__ __forceinline__ void ldsm2t(uint32_t* r, uint32_t a) {
    asm volatile("ldmatrix.sync.aligned.m8n8.x2.trans.shared.b16 {%0,%1}, [%2];"
                 : "=r"(r[0]), "=r"(r[1]) : "r"(a));
}
__device__ __forceinline__ void mma16816(float* d, const uint32_t* a, const uint32_t* b) {
    asm volatile(
        "mma.sync.aligned.m16n8k16.row.col.f32.f16.f16.f32 "
        "{%0,%1,%2,%3}, {%4,%5,%6,%7}, {%8,%9}, {%0,%1,%2,%3};"
        : "+f"(d[0]), "+f"(d[1]), "+f"(d[2]), "+f"(d[3])
        : "r"(a[0]), "r"(a[1]), "r"(a[2]), "r"(a[3]), "r"(b[0]), "r"(b[1]));
}
__device__ __forceinline__ uint32_t packh(float x, float y) {
    __half2 t = __floats2half2_rn(x, y);
    return *(uint32_t*)&t;
}
// packed 2^x on two fp16 lanes (single MUFU op)
__device__ __forceinline__ uint32_t ex2h2(uint32_t x) {
    uint32_t y;
    asm("ex2.approx.f16x2 %0, %1;" : "=r"(y) : "r"(x));
    return y;
}

// ---------------------------------------------------------------------------
// Conversions
// ---------------------------------------------------------------------------
__global__ void convert_act(const float* __restrict__ x0, const float* __restrict__ x1,
                            const float* __restrict__ x2)
{
    const int z = blockIdx.y;
    const float* x = (z == 0) ? x0 : (z == 1) ? x1 : x2;
    __half* dst = g_A + (size_t)z * MROWS * DD;

    const size_t i = (size_t)blockIdx.x * blockDim.x + threadIdx.x;
    float4 v = ((const float4*)x)[i];
    ((__half2*)dst)[2 * i + 0] = __floats2half2_rn(v.x, v.y);
    ((__half2*)dst)[2 * i + 1] = __floats2half2_rn(v.z, v.w);
}

// Weight transpose + round: Wt[n][k] = fp16(w[k][n])
__global__ void convert_wt(const float* __restrict__ w0, const float* __restrict__ w1,
                           const float* __restrict__ w2, const float* __restrict__ w3)
{
    __shared__ float t[32][33];
    const int z = blockIdx.z;
    const float* w = (z == 0) ? w0 : (z == 1) ? w1 : (z == 2) ? w2 : w3;
    const int nb = blockIdx.x * 32;
    const int kb = blockIdx.y * 32;

    for (int i = threadIdx.y; i < 32; i += 8)
        t[i][threadIdx.x] = w[(size_t)(kb + i) * DD + nb + threadIdx.x];
    __syncthreads();

    __half* wt = g_Wt + (size_t)z * DD * DD;
    for (int i = threadIdx.y; i < 32; i += 8)
        wt[(size_t)(nb + i) * DD + kb + threadIdx.x] = __float2half_rn(t[threadIdx.x][i]);
}

// ---------------------------------------------------------------------------
// HMMA single-fp16 GEMM: C = A @ W^T + bias   (R11-R14 tiling; single-sync
// pipeline. NEW: mode-0 epilogue stages the fp16 tile in smem, then copies
// out with 16B fully-coalesced stores (fragment-direct scatter was 50%
// sector efficiency).)
// CTA 128x128, K-chunk 32, 4 warps, warp-tile 64x64, 2-stage, 2 CTAs/SM.
// ---------------------------------------------------------------------------
#define PLANE_BYTES 10240           // 128 * 80
#define BUF_BYTES   (2 * PLANE_BYTES)
#define GEMM_SMEM   (2 * BUF_BYTES) // 40960
#define ESTRIDE     272             // epilogue stage row stride (128*2 + 16)

__global__ __launch_bounds__(128, 2)
void gemm_tc(const float* __restrict__ bias0, const float* __restrict__ bias1,
             const float* __restrict__ bias2, float* __restrict__ outExt, int mode)
{
    extern __shared__ __align__(128) char smem[];
    const uint32_t smemA = smem_u32(smem);

    const int tid  = threadIdx.x;
    const int wid  = tid >> 5;
    const int lane = tid & 31;
    const int wm   = wid >> 1;
    const int wn   = wid & 1;
    const int z    = blockIdx.z;
    const int mBase = blockIdx.x * 128;
    const int nBase = blockIdx.y * 128;

    const __half* A = (mode == 0) ? (g_A + (size_t)z * MROWS * DD) : g_Oh;
    const int widx = (mode == 0) ? z : 3;
    const __half* W = g_Wt + (size_t)widx * DD * DD;
    const float* bias = (z == 0) ? bias0 : (z == 1) ? bias1 : bias2;

    const __half* srcs[2] = {A, W};

    auto load_chunk = [&](int buf, int k0) {
        char* bb = smem + buf * BUF_BYTES;
        #pragma unroll
        for (int it = 0; it < 8; it++) {
            const int idx = it * 128 + tid;      // 0..1023
            const int p   = idx >> 9;            // 0 = A; 1 = W
            const int r   = idx & 511;
            const int row = r >> 2;
            const int seg = r & 3;
            const int rowBase = (p == 0) ? mBase : nBase;
            const __half* g = srcs[p] + (size_t)(rowBase + row) * DD + k0 + seg * 8;
            cp_async16(smem_u32(bb + p * PLANE_BYTES + row * 80 + seg * 16), g);
        }
    };

    float acc[4][8][4];
    #pragma unroll
    for (int t = 0; t < 4; t++)
        #pragma unroll
        for (int n = 0; n < 8; n++)
            #pragma unroll
            for (int j = 0; j < 4; j++) acc[t][n][j] = 0.f;

    const int aRow = lane & 15;
    const int aCol = (lane >> 4) * 16;
    const int bRow = (lane & 7) + ((lane >> 4) << 3);
    const int bCol = ((lane >> 3) & 1) * 16;

    const int NC = DD / 32;   // 32 chunks

    load_chunk(0, 0);
    cp_commit();

    for (int c = 0; c < NC; c++) {
        const int buf = c & 1;
        cp_wait<0>();
        __syncthreads();   // visibility of tile c + all readers of buf^1 done
        if (c + 1 < NC) {
            load_chunk(buf ^ 1, (c + 1) * 32);
            cp_commit();
        }

        const uint32_t base = smemA + buf * BUF_BYTES;
        #pragma unroll
        for (int s = 0; s < 2; s++) {
            uint32_t ah[4][4], bh[8][2];
            #pragma unroll
            for (int t = 0; t < 4; t++)
                ldsm4(ah[t], base + (wm * 64 + t * 16 + aRow) * 80 + s * 32 + aCol);
            #pragma unroll
            for (int bt = 0; bt < 4; bt++) {
                const uint32_t addr = base + PLANE_BYTES
                                    + (wn * 64 + bt * 16 + bRow) * 80 + s * 32 + bCol;
                uint32_t r4[4];
                ldsm4(r4, addr);
                bh[bt * 2][0] = r4[0]; bh[bt * 2][1] = r4[1];
                bh[bt * 2 + 1][0] = r4[2]; bh[bt * 2 + 1][1] = r4[3];
            }
            #pragma unroll
            for (int t = 0; t < 4; t++)
                #pragma unroll
                for (int n = 0; n < 8; n++)
                    mma16816(acc[t][n], ah[t], bh[n]);
        }
    }

    // ---- epilogue ----
    const float csc = (mode == 0 && z == 0) ? QSCALE : 1.0f;

    if (mode == 0) {
        // Stage bias+scaled fp16 tile in smem (conflict-free: stride 272B
        // => bank = 4*row + (lane&3), distinct per warp-store).
        __syncthreads();   // staging region overlaps buffer 1; wait for laggards
        #pragma unroll
        for (int t = 0; t < 4; t++) {
            #pragma unroll
            for (int n = 0; n < 8; n++) {
                const int colL = wn * 64 + n * 8 + (lane & 3) * 2;
                const int col = nBase + colL;
                const float b0v = bias[col];
                const float b1v = bias[col + 1];
                #pragma unroll
                for (int half = 0; half < 2; half++) {
                    const int rowL = wm * 64 + t * 16 + half * 8 + (lane >> 2);
                    float v0 = (acc[t][n][half * 2 + 0] + b0v) * csc;
                    float v1 = (acc[t][n][half * 2 + 1] + b1v) * csc;
                    *(__half2*)(smem + rowL * ESTRIDE + colL * 2) =
                        __floats2half2_rn(v0, v1);
                }
            }
        }
        __syncthreads();
        // Coalesced head-split copy: 8 threads cover one 128B (row,head) run.
        __half* ph = g_Ph + (size_t)z * BB * HH * SS * DK;
        const int h0 = nBase >> 6;
        #pragma unroll
        for (int it = 0; it < 16; it++) {
            const int tsk  = it * 128 + tid;     // 0..2047
            const int row  = tsk >> 4;
            const int head = (tsk >> 3) & 1;
            const int seg  = tsk & 7;
            int4 v = *(int4*)(smem + row * ESTRIDE + head * 128 + seg * 16);
            const int gm = mBase + row;
            const int b = gm >> 11;
            const int s = gm & 2047;
            *(int4*)(ph + (((size_t)(b * HH + h0 + head)) * SS + s) * DK + seg * 8) = v;
        }
    } else {
        // O-proj: fragment-direct float2 stores already form full 32B sectors.
        const int rBase = mBase + wm * 64 + (lane >> 2);
        const int cBase = nBase + wn * 64 + (lane & 3) * 2;
        #pragma unroll
        for (int t = 0; t < 4; t++) {
            #pragma unroll
            for (int n = 0; n < 8; n++) {
                const int col = cBase + n * 8;
                const float b0v = bias[col];
                const float b1v = bias[col + 1];
                #pragma unroll
                for (int half = 0; half < 2; half++) {
                    const int row = rBase + t * 16 + half * 8;
                    float2 v;
                    v.x = acc[t][n][half * 2 + 0] + b0v;
                    v.y = acc[t][n][half * 2 + 1] + b1v;
                    *(float2*)&outExt[(size_t)row * DD + col] = v;
                }
            }
        }
    }
}

// ---------------------------------------------------------------------------
// Tensor-core flash attention. R13/R14 config (4 warps x 32 q-rows, f16x2
// exp, ones-column row-sum, single-sync pipeline). NEW: epilogue stages the
// normalized fp16 output in smem buffer 0 (disjoint from final tile's
// buffer 1), then copies with 16B coalesced stores.
// Smem: K,V planes 64 rows x 144B, double buffered = 36864 B. 2 CTAs/SM.
// ---------------------------------------------------------------------------
#define ARS    144                  // attn smem row stride (bytes)
#define APLANE (64 * ARS)           // 9216
#define ABUF   (2 * APLANE)         // 18432
#define ATTN_SMEM (2 * ABUF)        // 36864

__global__ __launch_bounds__(128, 2)
void attn_tc()
{
    extern __shared__ __align__(128) char smem[];
    const uint32_t smemA = smem_u32(smem);

    const int tid  = threadIdx.x;
    const int wid  = tid >> 5;       // 0..3, owns q-rows wid*32 .. wid*32+31
    const int lane = tid & 31;
    const int b = blockIdx.z;
    const int h = blockIdx.y;
    const int qBase = blockIdx.x * 128;

    const size_t hb = ((size_t)(b * HH + h)) * SS * DK;
    const size_t PS = (size_t)BB * HH * SS * DK;
    const __half* Qh = g_Ph + hb;
    const __half* Kh = g_Ph + PS + hb;
    const __half* Vh = g_Ph + 2 * PS + hb;

    // ---- stage Q (128 rows x 64 dk) through smem, load to regs ----
    {
        #pragma unroll
        for (int it = 0; it < 8; it++) {
            const int idx = it * 128 + tid;        // 0..1023
            const int row = idx >> 3;
            const int seg = idx & 7;
            cp_async16(smemA + row * ARS + seg * 16,
                       Qh + (size_t)(qBase + row) * DK + seg * 8);
        }
        cp_commit();
        cp_wait<0>();
        __syncthreads();
    }

    uint32_t qh[2][4][4];    // [q-subtile][dk-slice][frag]
    {
        const int aRow = lane & 15;
        const int aCol = (lane >> 4) * 16;
        #pragma unroll
        for (int u = 0; u < 2; u++)
            #pragma unroll
            for (int s = 0; s < 4; s++)
                ldsm4(qh[u][s],
                      smemA + (wid * 32 + u * 16 + aRow) * ARS + s * 32 + aCol);
    }
    __syncthreads();   // Q regs extracted; smem reusable

    // ---- ones column: V-plane padding bytes [128..144) of every row gets
    // {1.0h, 0,...}. cp.async only writes bytes [0..128) per row, so these
    // persist once set.
    {
        const int st  = tid >> 6;                 // 0..1 (stage)
        const int row = tid & 63;
        int4 ones = make_int4(0x00003C00, 0, 0, 0);
        *(int4*)(smem + st * ABUF + APLANE + row * ARS + 128) = ones;
    }

    // ---- K/V tile loader ----
    auto load_kv = [&](int buf, int t0) {
        char* bb = smem + buf * ABUF;
        #pragma unroll
        for (int it = 0; it < 8; it++) {
            const int idx = it * 128 + tid;        // 0..1023
            const int p   = idx >> 9;              // 0=K 1=V
            const int r   = idx & 511;
            const int row = r >> 3;
            const int seg = r & 7;
            const __half* g = (p ? Vh : Kh) + (size_t)(t0 + row) * DK + seg * 8;
            cp_async16(smem_u32(bb + p * APLANE + row * ARS + seg * 16), g);
        }
    };

    float oacc[2][8][4];
    #pragma unroll
    for (int u = 0; u < 2; u++)
        #pragma unroll
        for (int n = 0; n < 8; n++)
            #pragma unroll
            for (int j = 0; j < 4; j++) oacc[u][n][j] = 0.f;
    float oext[2][4];
    #pragma unroll
    for (int u = 0; u < 2; u++)
        #pragma unroll
        for (int j = 0; j < 4; j++) oext[u][j] = 0.f;

    const int bRow = (lane & 7) + ((lane >> 4) << 3);
    const int bCol = ((lane >> 3) & 1) * 16;
    const int vRow = lane & 15;
    const int vCol = (lane >> 4) * 16;

    load_kv(0, 0);
    cp_commit();

    const int NT = SS / 64;   // 32 key tiles

    for (int t = 0; t < NT; t++) {
        const int buf = t & 1;
        cp_wait<0>();
        __syncthreads();   // visibility of tile t + all readers of buf^1 done
        if (t + 1 < NT) {
            load_kv(buf ^ 1, (t + 1) * 64);
            cp_commit();
        }

        const uint32_t kbase = smemA + buf * ABUF;
        const uint32_t vbase = kbase + APLANE;

        // ---- S = Q K^T (K fragments shared across both q-subtiles) ----
        float sc[2][8][4];
        #pragma unroll
        for (int u = 0; u < 2; u++)
            #pragma unroll
            for (int n = 0; n < 8; n++)
                #pragma unroll
                for (int j = 0; j < 4; j++) sc[u][n][j] = 0.f;

        #pragma unroll
        for (int s = 0; s < 4; s++) {
            uint32_t bh[8][2];
            #pragma unroll
            for (int bt = 0; bt < 4; bt++) {
                const uint32_t addr = kbase + (bt * 16 + bRow) * ARS + s * 32 + bCol;
                uint32_t r4[4];
                ldsm4(r4, addr);
                bh[bt * 2][0] = r4[0]; bh[bt * 2][1] = r4[1];
                bh[bt * 2 + 1][0] = r4[2]; bh[bt * 2 + 1][1] = r4[3];
            }
            #pragma unroll
            for (int u = 0; u < 2; u++)
                #pragma unroll
                for (int n = 0; n < 8; n++)
                    mma16816(sc[u][n], qh[u][s], bh[n]);
        }

        // ---- O += P V with P = 2^S in packed fp16; l via ones column ----
        #pragma unroll
        for (int j = 0; j < 4; j++) {
            uint32_t vb[8][2];
            #pragma unroll
            for (int d = 0; d < 4; d++) {
                const uint32_t addr = vbase + (j * 16 + vRow) * ARS + d * 32 + vCol;
                uint32_t r4[4];
                ldsm4t(r4, addr);
                vb[d * 2][0] = r4[0]; vb[d * 2][1] = r4[1];
                vb[d * 2 + 1][0] = r4[2]; vb[d * 2 + 1][1] = r4[3];
            }
            uint32_t ob[2];
            ldsm2t(ob, vbase + (j * 16 + vRow) * ARS + 128);

            #pragma unroll
            for (int u = 0; u < 2; u++) {
                uint32_t aph[4];
                aph[0] = ex2h2(packh(sc[u][2*j][0],   sc[u][2*j][1]));
                aph[1] = ex2h2(packh(sc[u][2*j][2],   sc[u][2*j][3]));
                aph[2] = ex2h2(packh(sc[u][2*j+1][0], sc[u][2*j+1][1]));
                aph[3] = ex2h2(packh(sc[u][2*j+1][2], sc[u][2*j+1][3]));
                #pragma unroll
                for (int n = 0; n < 8; n++)
                    mma16816(oacc[u][n], aph, vb[n]);
                mma16816(oext[u], aph, ob);
            }
        }
    }

    // ---- epilogue: normalize, stage fp16 tile in smem buf 0, coalesced copy ----
    __syncthreads();   // insurance: all warps past their last buf-0 reads
    #pragma unroll
    for (int u = 0; u < 2; u++) {
        const float l0v = __shfl_sync(0xffffffffu, oext[u][0], lane & 28);
        const float l1v = __shfl_sync(0xffffffffu, oext[u][2], lane & 28);
        const float inv0 = 1.f / l0v;
        const float inv1 = 1.f / l1v;
        #pragma unroll
        for (int n = 0; n < 8; n++) {
            const int colL = n * 8 + (lane & 3) * 2;
            const int r0 = wid * 32 + u * 16 + (lane >> 2);
            *(__half2*)(smem + r0 * ARS + colL * 2) =
                __floats2half2_rn(oacc[u][n][0] * inv0, oacc[u][n][1] * inv0);
            *(__half2*)(smem + (r0 + 8) * ARS + colL * 2) =
                __floats2half2_rn(oacc[u][n][2] * inv1, oacc[u][n][3] * inv1);
        }
    }
    __syncthreads();
    // 128 rows x 128B contiguous runs; 8 threads per run.
    {
        __half* dst = g_Oh + (size_t)(b * SS + qBase) * DD + h * 64;
        #pragma unroll
        for (int it = 0; it < 8; it++) {
            const int tsk = it * 128 + tid;      // 0..1023
            const int row = tsk >> 3;
            const int seg = tsk & 7;
            int4 v = *(int4*)(smem + row * ARS + seg * 16);
            *(int4*)(dst + (size_t)row * DD + seg * 8) = v;
        }
    }
}

// ---------------------------------------------------------------------------
extern "C" void kernel_launch(void* const* d_in, const int* in_sizes, int n_in,
                              void* d_out, int out_size)
{
    const float* q  = (const float*)d_in[0];
    const float* k  = (const float*)d_in[1];
    const float* v  = (const float*)d_in[2];
    const float* wq = (const float*)d_in[3];
    const float* bq = (const float*)d_in[4];
    const float* wk = (const float*)d_in[5];
    const float* bk = (const float*)d_in[6];
    const float* wv = (const float*)d_in[7];
    const float* bv = (const float*)d_in[8];
    const float* wo = (const float*)d_in[9];
    const float* bo = (const float*)d_in[10];
    float* out = (float*)d_out;

    cudaFuncSetAttribute(gemm_tc, cudaFuncAttributeMaxDynamicSharedMemorySize, GEMM_SMEM);
    cudaFuncSetAttribute(attn_tc, cudaFuncAttributeMaxDynamicSharedMemorySize, ATTN_SMEM);

    // 1) Round activations to fp16; transpose+round weights to fp16
    convert_act<<<dim3(MROWS * DD / 4 / 256, 3), 256>>>(q, k, v);
    convert_wt<<<dim3(32, 32, 4), dim3(32, 8)>>>(wq, wk, wv, wo);

    // 2) QKV projections -> fp16 head-split (Q pre-scaled by 0.125*log2e)
    gemm_tc<<<dim3(MROWS / 128, DD / 128, 3), 128, GEMM_SMEM>>>(bq, bk, bv, nullptr, 0);

    // 3) Tensor-core flash attention -> g_Oh
    attn_tc<<<dim3(SS / 128, HH, BB), 128, ATTN_SMEM>>>();

    // 4) O projection
    gemm_tc<<<dim3(MROWS / 128, DD / 128, 1), 128, GEMM_SMEM>>>(bo, bo, bo, out, 1);
}